// round 3
// baseline (speedup 1.0000x reference)
#include <cuda_runtime.h>
#include <cuda_bf16.h>
#include <math.h>

#define NROWS 1048576
#define DTOT  64
#define DD    32
#define KK    40
#define BB    5.0f
#define NCELL 256
#define CELL_SCALE (NCELL / (2.0f * BB))   // 25.6

// Precomputed packed tables
__device__ float4        g_t0[DD * KK];   // {cumw, 1/bw, cumh, bh}
__device__ float2        g_t1[DD * KK];   // {d0, d1}
__device__ unsigned char g_lut[DD * NCELL];

// ---------------------------------------------------------------------------
// Precompute: softmax->cumsum tables, softplus derivs, packed per-bin structs,
// and a 256-cell uniform-grid bin LUT per dim. One thread per dim; runs once.
// ---------------------------------------------------------------------------
__global__ void precompute_tables(const float* __restrict__ w,
                                  const float* __restrict__ h,
                                  const float* __restrict__ dk)
{
    int j = threadIdx.x;
    if (j >= DD) return;

    float widths[KK], cumw[KK + 1];
    float heights[KK], cumh[KK + 1];
    float derivs[KK + 1];

    // widths: softmax(w) * 2B, cumsum
    {
        const float* row = w + j * KK;
        float mx = -1e30f;
        for (int k = 0; k < KK; k++) mx = fmaxf(mx, row[k]);
        float s = 0.f;
        for (int k = 0; k < KK; k++) s += expf(row[k] - mx);
        float inv_s = (2.0f * BB) / s;
        float cum = -BB;
        cumw[0] = -BB;
        for (int k = 0; k < KK; k++) {
            widths[k] = expf(row[k] - mx) * inv_s;
            cum += widths[k];
            cumw[k + 1] = cum;
        }
    }
    // heights
    {
        const float* row = h + j * KK;
        float mx = -1e30f;
        for (int k = 0; k < KK; k++) mx = fmaxf(mx, row[k]);
        float s = 0.f;
        for (int k = 0; k < KK; k++) s += expf(row[k] - mx);
        float inv_s = (2.0f * BB) / s;
        float cum = -BB;
        cumh[0] = -BB;
        for (int k = 0; k < KK; k++) {
            heights[k] = expf(row[k] - mx) * inv_s;
            cum += heights[k];
            cumh[k + 1] = cum;
        }
    }
    // derivatives: [1, softplus(d), 1]
    derivs[0] = 1.0f;
    derivs[KK] = 1.0f;
    {
        const float* row = dk + j * (KK - 1);
        for (int k = 0; k < KK - 1; k++) {
            float v = row[k];
            derivs[k + 1] = (v > 20.0f) ? v : log1pf(expf(v));
        }
    }

    // packed per-bin structs
    for (int k = 0; k < KK; k++) {
        float4 t0;
        t0.x = cumw[k];
        t0.y = 1.0f / widths[k];
        t0.z = cumh[k];
        t0.w = heights[k];
        g_t0[j * KK + k] = t0;
        g_t1[j * KK + k] = make_float2(derivs[k], derivs[k + 1]);
    }

    // LUT: bin index of each cell's LEFT edge (conservative; fixup moves right)
    {
        int idx = 0;
        for (int c = 0; c < NCELL; c++) {
            float left = -BB + (float)c * (2.0f * BB / NCELL);
            while (idx < KK - 1 && cumw[idx + 1] <= left) idx++;
            g_lut[j * NCELL + c] = (unsigned char)idx;
        }
    }
}

// ---------------------------------------------------------------------------
// Main kernel: one warp per row; lane handles cols {lane, lane+32}.
// ---------------------------------------------------------------------------
__global__ __launch_bounds__(256)
void rqs_forward_kernel(const float* __restrict__ u,
                        const int*   __restrict__ nodes,
                        float* __restrict__ xout,
                        float* __restrict__ logd)
{
    __shared__ float4        s_t0[DD * KK];     // 20 KB
    __shared__ float2        s_t1[DD * KK];     // 10 KB
    __shared__ unsigned char s_lut[DD * NCELL]; //  8 KB
    __shared__ int           s_inv[DTOT];

    const int tid = threadIdx.x;

    for (int i = tid; i < DD * KK; i += blockDim.x) {
        s_t0[i] = g_t0[i];
        s_t1[i] = g_t1[i];
    }
    for (int i = tid; i < DD * NCELL / 4; i += blockDim.x)
        ((uchar4*)s_lut)[i] = ((const uchar4*)g_lut)[i];
    if (tid < DTOT) s_inv[tid] = -1;
    __syncthreads();
    if (tid < DD) s_inv[nodes[tid]] = tid;
    __syncthreads();

    const float* s_t0x = (const float*)s_t0;   // scalar view for fixup probe

    const int lane = tid & 31;
    const int warp = tid >> 5;
    const int rows_per_iter = blockDim.x >> 5;   // 8

    for (unsigned row = blockIdx.x * rows_per_iter + warp; row < NROWS;
         row += gridDim.x * rows_per_iter)
    {
        const float* up = u    + (size_t)row * DTOT;
        float*       xp = xout + (size_t)row * DTOT;
        float acc = 0.0f;

        #pragma unroll
        for (int half = 0; half < 2; half++) {
            const int col = lane + half * 32;
            const float x = __ldg(up + col);
            const int j = s_inv[col];
            float y = x;

            if (j >= 0 && fabsf(x) <= BB) {
                const float xc = x;
                // uniform-grid LUT seed + up to 2 predicated fixups
                int cell = (int)((xc + BB) * CELL_SCALE);
                cell = min(max(cell, 0), NCELL - 1);
                int idx = (int)s_lut[j * NCELL + cell];
                const int base = j * KK;
                #pragma unroll
                for (int f = 0; f < 2; f++) {
                    bool adv = (idx < KK - 1) && (s_t0x[(base + idx + 1) * 4] <= xc);
                    idx += adv ? 1 : 0;
                }

                const float4 t0 = s_t0[base + idx];  // cw, 1/bw, ch, bh
                const float2 t1 = s_t1[base + idx];  // d0, d1

                const float rbw  = t0.y;
                const float bh   = t0.w;
                const float d0   = t1.x;
                const float d1   = t1.y;

                const float delta = bh * rbw;
                const float theta = (xc - t0.x) * rbw;
                const float omt   = 1.0f - theta;
                const float t1m   = theta * omt;

                const float denom = fmaf(d0 + d1 - 2.0f * delta, t1m, delta);
                const float r     = __fdividef(1.0f, denom);

                y = fmaf(bh * fmaf(delta * theta, theta, d0 * t1m), r, t0.z);

                const float A = delta * delta *
                    (fmaf(d1 * theta, theta, 2.0f * delta * t1m) + d0 * omt * omt);
                acc += __logf(A * r * r);
            }
            xp[col] = y;
        }

        // warp-level logdet reduction (full row lives in this warp)
        #pragma unroll
        for (int o = 16; o > 0; o >>= 1)
            acc += __shfl_down_sync(0xffffffffu, acc, o);
        if (lane == 0) logd[row] = acc;
    }
}

extern "C" void kernel_launch(void* const* d_in, const int* in_sizes, int n_in,
                              void* d_out, int out_size)
{
    const float* u     = (const float*)d_in[0];
    const float* w     = (const float*)d_in[1];
    const float* h     = (const float*)d_in[2];
    const float* dk    = (const float*)d_in[3];
    const int*   nodes = (const int*)  d_in[4];

    float* xout = (float*)d_out;
    float* logd = xout + (size_t)NROWS * DTOT;

    precompute_tables<<<1, 32>>>(w, h, dk);

    const int block = 256;
    const int grid  = 740;   // 5 blocks/SM x 148 SMs, persistent grid-stride
    rqs_forward_kernel<<<grid, block>>>(u, nodes, xout, logd);
}

// round 4
// speedup vs baseline: 1.5095x; 1.5095x over previous
#include <cuda_runtime.h>
#include <cuda_bf16.h>
#include <math.h>

#define NROWS 1048576
#define DTOT  64
#define DD    32
#define KK    40
#define T0S   41                    // padded stride (sentinel at [40])
#define BB    5.0f
#define NCELL 128
#define CELL_SCALE (NCELL / (2.0f * BB))   // 12.8

// Precomputed packed tables
__device__ float4        g_t0[DD * T0S];   // {cumw, 1/bw, cumh, bh}; [40] = sentinel cw=+INF
__device__ float2        g_t1[DD * T0S];   // {d0, d1}
__device__ unsigned char g_lut[DD * NCELL];

// ---------------------------------------------------------------------------
// Precompute. Phase A: 32 threads build softmax/cumsum/softplus tables.
// Phase B: all 256 threads build the 128-cell LUT via binary search (parallel).
// ---------------------------------------------------------------------------
__global__ void precompute_tables(const float* __restrict__ w,
                                  const float* __restrict__ h,
                                  const float* __restrict__ dk)
{
    __shared__ float s_cumw[DD][KK + 1];
    const int tid = threadIdx.x;

    if (tid < DD) {
        const int j = tid;
        float widths[KK], cumw[KK + 1];
        float cumh[KK + 1];
        float derivs[KK + 1];

        // widths: softmax(w) * 2B, cumsum
        {
            const float* row = w + j * KK;
            float mx = -1e30f;
            for (int k = 0; k < KK; k++) mx = fmaxf(mx, row[k]);
            float s = 0.f;
            for (int k = 0; k < KK; k++) s += expf(row[k] - mx);
            float inv_s = (2.0f * BB) / s;
            float cum = -BB;
            cumw[0] = -BB;
            for (int k = 0; k < KK; k++) {
                widths[k] = expf(row[k] - mx) * inv_s;
                cum += widths[k];
                cumw[k + 1] = cum;
            }
        }
        // heights
        {
            const float* row = h + j * KK;
            float mx = -1e30f;
            for (int k = 0; k < KK; k++) mx = fmaxf(mx, row[k]);
            float s = 0.f;
            for (int k = 0; k < KK; k++) s += expf(row[k] - mx);
            float inv_s = (2.0f * BB) / s;
            float cum = -BB;
            cumh[0] = -BB;
            for (int k = 0; k < KK; k++) {
                cum += expf(row[k] - mx) * inv_s;
                cumh[k + 1] = cum;
            }
        }
        // derivatives: [1, softplus(d), 1]
        derivs[0] = 1.0f;
        derivs[KK] = 1.0f;
        {
            const float* row = dk + j * (KK - 1);
            for (int k = 0; k < KK - 1; k++) {
                float v = row[k];
                derivs[k + 1] = (v > 20.0f) ? v : log1pf(expf(v));
            }
        }

        for (int k = 0; k < KK; k++) {
            float4 t0;
            t0.x = cumw[k];
            t0.y = 1.0f / widths[k];
            t0.z = cumh[k];
            t0.w = cumh[k + 1] - cumh[k];
            g_t0[j * T0S + k] = t0;
            g_t1[j * T0S + k] = make_float2(derivs[k], derivs[k + 1]);
        }
        // sentinel: probe of cw[idx+1] at idx=39 must never advance
        g_t0[j * T0S + KK] = make_float4(__int_as_float(0x7f800000), 1.f, 0.f, 1.f);
        g_t1[j * T0S + KK] = make_float2(1.f, 1.f);

        for (int k = 0; k <= KK; k++) s_cumw[j][k] = cumw[k];
    }
    __syncthreads();

    // Phase B: LUT — bin index valid at (cell left edge - eps); fixup moves right.
    for (int i = tid; i < DD * NCELL; i += blockDim.x) {
        const int j = i / NCELL;
        const int c = i % NCELL;
        const float left = -BB + (float)c * (2.0f * BB / NCELL) - 1e-4f;
        int lo = 0, hi = KK;             // largest idx with cumw[idx] <= left
        #pragma unroll
        for (int it = 0; it < 6; it++) {
            int mid = (lo + hi) >> 1;
            if (s_cumw[j][mid] <= left) lo = mid; else hi = mid;
        }
        g_lut[i] = (unsigned char)min(lo, KK - 1);
    }
}

// ---------------------------------------------------------------------------
// Main kernel: one warp per 2 rows per trip; lane handles cols {lane, lane+32}
// of both rows -> 4 independent dependency chains per lane.
// ---------------------------------------------------------------------------
__global__ __launch_bounds__(256, 5)
void rqs_forward_kernel(const float* __restrict__ u,
                        const int*   __restrict__ nodes,
                        float* __restrict__ xout,
                        float* __restrict__ logd)
{
    __shared__ float4        s_t0[DD * T0S];     // 21 KB
    __shared__ float2        s_t1[DD * T0S];     // 10.5 KB
    __shared__ unsigned char s_lut[DD * NCELL];  //  4 KB
    __shared__ int           s_inv[DTOT];

    const int tid = threadIdx.x;

    for (int i = tid; i < DD * T0S; i += blockDim.x) {
        s_t0[i] = g_t0[i];
        s_t1[i] = g_t1[i];
    }
    for (int i = tid; i < DD * NCELL / 4; i += blockDim.x)
        ((uchar4*)s_lut)[i] = ((const uchar4*)g_lut)[i];
    if (tid < DTOT) s_inv[tid] = -1;
    __syncthreads();
    if (tid < DD) s_inv[nodes[tid]] = tid;
    __syncthreads();

    const float* s_t0x = (const float*)s_t0;   // scalar view for boundary probe

    const int lane = tid & 31;
    const int warp = tid >> 5;

    const int j0 = s_inv[lane];         // dim for col = lane
    const int j1 = s_inv[lane + 32];    // dim for col = lane + 32

    const unsigned gw     = blockIdx.x * 8 + warp;       // global warp id
    const unsigned stride = gridDim.x * 16;              // rows per grid trip

    for (unsigned r0 = gw * 2; r0 < NROWS; r0 += stride)
    {
        const unsigned r1 = r0 + 1;     // NROWS even; always valid
        const float* up0 = u + (size_t)r0 * DTOT;
        const float* up1 = u + (size_t)r1 * DTOT;

        float xv[4], yv[4];
        xv[0] = __ldg(up0 + lane);
        xv[1] = __ldg(up0 + lane + 32);
        xv[2] = __ldg(up1 + lane);
        xv[3] = __ldg(up1 + lane + 32);

        float acc0 = 0.0f, acc1 = 0.0f;

        #pragma unroll
        for (int e = 0; e < 4; e++) {
            const int   j = (e & 1) ? j1 : j0;
            const float x = xv[e];
            float y = x;

            if (j >= 0 && fabsf(x) <= BB) {
                // uniform-grid LUT seed + exactly one predicated fixup
                int cell = min((int)((x + BB) * CELL_SCALE), NCELL - 1);
                int idx  = (int)s_lut[j * NCELL + cell];
                const int base = j * T0S;
                // sentinel at [40] (= +INF) makes the guard unnecessary
                idx += (s_t0x[(base + idx + 1) * 4] <= x) ? 1 : 0;

                const float4 t0 = s_t0[base + idx];  // cw, 1/bw, ch, bh
                const float2 t1 = s_t1[base + idx];  // d0, d1

                const float rbw  = t0.y;
                const float bh   = t0.w;
                const float d0   = t1.x;
                const float d1   = t1.y;

                const float delta = bh * rbw;
                const float theta = (x - t0.x) * rbw;
                const float omt   = 1.0f - theta;
                const float t1m   = theta * omt;

                const float denom = fmaf(d0 + d1 - 2.0f * delta, t1m, delta);
                const float r     = __fdividef(1.0f, denom);

                y = fmaf(bh * fmaf(delta * theta, theta, d0 * t1m), r, t0.z);

                const float A = delta * delta *
                    (fmaf(d1 * theta, theta, 2.0f * delta * t1m) + d0 * omt * omt);
                const float ld = __logf(A * r * r);
                if (e < 2) acc0 += ld; else acc1 += ld;
            }
            yv[e] = y;
        }

        float* xp0 = xout + (size_t)r0 * DTOT;
        float* xp1 = xout + (size_t)r1 * DTOT;
        xp0[lane]      = yv[0];
        xp0[lane + 32] = yv[1];
        xp1[lane]      = yv[2];
        xp1[lane + 32] = yv[3];

        // warp-level logdet reductions (one full row per acc)
        #pragma unroll
        for (int o = 16; o > 0; o >>= 1) {
            acc0 += __shfl_down_sync(0xffffffffu, acc0, o);
            acc1 += __shfl_down_sync(0xffffffffu, acc1, o);
        }
        if (lane == 0) {
            logd[r0] = acc0;
            logd[r1] = acc1;
        }
    }
}

extern "C" void kernel_launch(void* const* d_in, const int* in_sizes, int n_in,
                              void* d_out, int out_size)
{
    const float* u     = (const float*)d_in[0];
    const float* w     = (const float*)d_in[1];
    const float* h     = (const float*)d_in[2];
    const float* dk    = (const float*)d_in[3];
    const int*   nodes = (const int*)  d_in[4];

    float* xout = (float*)d_out;
    float* logd = xout + (size_t)NROWS * DTOT;

    precompute_tables<<<1, 256>>>(w, h, dk);

    const int block = 256;
    const int grid  = 740;   // 5 CTAs/SM x 148 SMs, persistent grid-stride
    rqs_forward_kernel<<<grid, block>>>(u, nodes, xout, logd);
}

// round 6
// speedup vs baseline: 1.8107x; 1.1995x over previous
#include <cuda_runtime.h>
#include <cuda_bf16.h>
#include <math.h>

#define NROWS 1048576
#define DTOT  64
#define DD    32
#define KK    40
#define BB    5.0f
#define NCELL 128
#define CELL_SCALE (NCELL / (2.0f * BB))   // 12.8

// Transposed tables: [idx][dim] so that shared-memory banks depend only on the
// (distinct-per-lane) dim, never on the data-dependent bin index.
__device__ float         g_bndT[(KK + 2) * DD];   // cumw boundaries; [KK+1] row = +INF probe sentinel... [k][j], k=0..40 real/INF
__device__ float4        g_t0T [KK * DD];          // {rbw, cumh(left), bh, d0}
__device__ float         g_d1T [KK * DD];          // d1
__device__ unsigned char g_lutT[NCELL * DD];       // bin idx of cell left edge

// ---------------------------------------------------------------------------
// Precompute. Phase A: 32 threads build softmax/cumsum/softplus tables
// (transposed). Phase B: all 256 threads build the 128-cell LUT in parallel.
// ---------------------------------------------------------------------------
__global__ void precompute_tables(const float* __restrict__ w,
                                  const float* __restrict__ h,
                                  const float* __restrict__ dk)
{
    __shared__ float s_cumw[DD][KK + 1];
    const int tid = threadIdx.x;

    if (tid < DD) {
        const int j = tid;
        float widths[KK], cumw[KK + 1];
        float cumh[KK + 1];
        float derivs[KK + 1];

        // widths: softmax(w) * 2B, cumsum
        {
            const float* row = w + j * KK;
            float mx = -1e30f;
            for (int k = 0; k < KK; k++) mx = fmaxf(mx, row[k]);
            float s = 0.f;
            for (int k = 0; k < KK; k++) s += expf(row[k] - mx);
            float inv_s = (2.0f * BB) / s;
            float cum = -BB;
            cumw[0] = -BB;
            for (int k = 0; k < KK; k++) {
                widths[k] = expf(row[k] - mx) * inv_s;
                cum += widths[k];
                cumw[k + 1] = cum;
            }
        }
        // heights
        {
            const float* row = h + j * KK;
            float mx = -1e30f;
            for (int k = 0; k < KK; k++) mx = fmaxf(mx, row[k]);
            float s = 0.f;
            for (int k = 0; k < KK; k++) s += expf(row[k] - mx);
            float inv_s = (2.0f * BB) / s;
            float cum = -BB;
            cumh[0] = -BB;
            for (int k = 0; k < KK; k++) {
                cum += expf(row[k] - mx) * inv_s;
                cumh[k + 1] = cum;
            }
        }
        // derivatives: [1, softplus(d), 1]
        derivs[0] = 1.0f;
        derivs[KK] = 1.0f;
        {
            const float* row = dk + j * (KK - 1);
            for (int k = 0; k < KK - 1; k++) {
                float v = row[k];
                derivs[k + 1] = (v > 20.0f) ? v : log1pf(expf(v));
            }
        }

        // transposed writes
        for (int k = 0; k < KK; k++) {
            g_bndT[k * DD + j] = cumw[k];
            float4 t0;
            t0.x = 1.0f / widths[k];
            t0.y = cumh[k];
            t0.z = cumh[k + 1] - cumh[k];
            t0.w = derivs[k];
            g_t0T[k * DD + j] = t0;
            g_d1T[k * DD + j] = derivs[k + 1];
        }
        g_bndT[KK * DD + j]       = cumw[KK];                      // = +B (left-edge use only)
        g_bndT[(KK + 1) * DD + j] = __int_as_float(0x7f800000);    // unused pad
        // probe at idx=39 reads bnd[40] = +B; x <= B can equal B -> would
        // advance to idx=40. Replace the k=40 probe value with +INF; bin 39's
        // left edge is k=39 so nothing else reads k=40.
        g_bndT[KK * DD + j] = __int_as_float(0x7f800000);

        for (int k = 0; k <= KK; k++) s_cumw[j][k] = cumw[k];
    }
    __syncthreads();

    // Phase B: LUT — bin index valid at (cell left edge - eps); fixup moves right.
    for (int i = tid; i < DD * NCELL; i += blockDim.x) {
        const int j = i / NCELL;
        const int c = i % NCELL;
        const float left = -BB + (float)c * (2.0f * BB / NCELL) - 1e-4f;
        int lo = 0, hi = KK;             // largest idx with cumw[idx] <= left
        #pragma unroll
        for (int it = 0; it < 6; it++) {
            int mid = (lo + hi) >> 1;
            if (s_cumw[j][mid] <= left) lo = mid; else hi = mid;
        }
        g_lutT[c * DD + j] = (unsigned char)min(lo, KK - 1);
    }
}

// ---------------------------------------------------------------------------
// Main kernel: one warp per 2 rows per trip; lane handles cols {lane, lane+32}.
// All shared tables are [idx][dim]-transposed -> conflict-free gathers.
// ---------------------------------------------------------------------------
__global__ __launch_bounds__(256, 6)
void rqs_forward_kernel(const float* __restrict__ u,
                        const int*   __restrict__ nodes,
                        float* __restrict__ xout,
                        float* __restrict__ logd)
{
    __shared__ float         s_bndT[(KK + 2) * DD];   // 5.25 KB
    __shared__ float4        s_t0T [KK * DD];          // 20 KB
    __shared__ float         s_d1T [KK * DD];          // 5 KB
    __shared__ unsigned char s_lutT[NCELL * DD];       // 4 KB
    __shared__ int           s_inv [DTOT];

    const int tid = threadIdx.x;

    for (int i = tid; i < KK * DD; i += blockDim.x) {
        s_t0T[i] = g_t0T[i];
        s_d1T[i] = g_d1T[i];
    }
    for (int i = tid; i < (KK + 2) * DD; i += blockDim.x) s_bndT[i] = g_bndT[i];
    for (int i = tid; i < NCELL * DD / 4; i += blockDim.x)
        ((uchar4*)s_lutT)[i] = ((const uchar4*)g_lutT)[i];
    if (tid < DTOT) s_inv[tid] = -1;
    __syncthreads();
    if (tid < DD) s_inv[nodes[tid]] = tid;
    __syncthreads();

    const int lane = tid & 31;
    const int warp = tid >> 5;

    const int j0 = s_inv[lane];         // dim for col = lane (distinct per lane)
    const int j1 = s_inv[lane + 32];    // dim for col = lane + 32

    const unsigned gw     = blockIdx.x * 8 + warp;       // global warp id
    const unsigned stride = gridDim.x * 16;              // rows per grid trip

    for (unsigned r0 = gw * 2; r0 < NROWS; r0 += stride)
    {
        const unsigned r1 = r0 + 1;     // NROWS even; always valid
        const float* up0 = u + (size_t)r0 * DTOT;
        const float* up1 = u + (size_t)r1 * DTOT;

        float xv[4], yv[4];
        xv[0] = __ldg(up0 + lane);
        xv[1] = __ldg(up0 + lane + 32);
        xv[2] = __ldg(up1 + lane);
        xv[3] = __ldg(up1 + lane + 32);

        float acc0 = 0.0f, acc1 = 0.0f;

        #pragma unroll
        for (int e = 0; e < 4; e++) {
            const int   j = (e & 1) ? j1 : j0;
            const float x = xv[e];
            float y = x;

            if (j >= 0 && fabsf(x) <= BB) {
                // uniform-grid LUT seed
                int cell = min(max((int)((x + BB) * CELL_SCALE), 0), NCELL - 1);
                const int idx0 = (int)s_lutT[cell * DD + j];

                // both candidate left boundaries in parallel (conflict-free)
                const float b0 = s_bndT[idx0 * DD + j];
                const float b1 = s_bndT[(idx0 + 1) * DD + j];   // +INF at k=40
                const bool  adv = (b1 <= x);
                const int   idx = idx0 + (adv ? 1 : 0);
                const float cw  = adv ? b1 : b0;

                const float4 t0 = s_t0T[idx * DD + j];  // rbw, ch, bh, d0
                const float  d1 = s_d1T[idx * DD + j];

                const float rbw = t0.x;
                const float bh  = t0.z;
                const float d0  = t0.w;

                const float delta = bh * rbw;
                const float theta = (x - cw) * rbw;
                const float omt   = 1.0f - theta;
                const float t1m   = theta * omt;

                const float denom = fmaf(d0 + d1 - 2.0f * delta, t1m, delta);
                const float r     = __fdividef(1.0f, denom);

                y = fmaf(bh * fmaf(delta * theta, theta, d0 * t1m), r, t0.y);

                const float A = delta * delta *
                    (fmaf(d1 * theta, theta, 2.0f * delta * t1m) + d0 * omt * omt);
                const float ld = __logf(A * r * r);
                if (e < 2) acc0 += ld; else acc1 += ld;
            }
            yv[e] = y;
        }

        float* xp0 = xout + (size_t)r0 * DTOT;
        float* xp1 = xout + (size_t)r1 * DTOT;
        xp0[lane]      = yv[0];
        xp0[lane + 32] = yv[1];
        xp1[lane]      = yv[2];
        xp1[lane + 32] = yv[3];

        // warp-level logdet reductions (one full row per acc)
        #pragma unroll
        for (int o = 16; o > 0; o >>= 1) {
            acc0 += __shfl_down_sync(0xffffffffu, acc0, o);
            acc1 += __shfl_down_sync(0xffffffffu, acc1, o);
        }
        if (lane == 0) {
            logd[r0] = acc0;
            logd[r1] = acc1;
        }
    }
}

extern "C" void kernel_launch(void* const* d_in, const int* in_sizes, int n_in,
                              void* d_out, int out_size)
{
    const float* u     = (const float*)d_in[0];
    const float* w     = (const float*)d_in[1];
    const float* h     = (const float*)d_in[2];
    const float* dk    = (const float*)d_in[3];
    const int*   nodes = (const int*)  d_in[4];

    float* xout = (float*)d_out;
    float* logd = xout + (size_t)NROWS * DTOT;

    precompute_tables<<<1, 256>>>(w, h, dk);

    const int block = 256;
    const int grid  = 888;   // 6 CTAs/SM x 148 SMs, persistent grid-stride
    rqs_forward_kernel<<<grid, block>>>(u, nodes, xout, logd);
}

// round 8
// speedup vs baseline: 1.9435x; 1.0733x over previous
#include <cuda_runtime.h>
#include <cuda_bf16.h>
#include <math.h>

#define NROWS 1048576
#define DTOT  64
#define DD    32
#define KK    40
#define BB    5.0f
#define NCELL 128
#define CELL_SCALE (NCELL / (2.0f * BB))   // 12.8

// ---------------------------------------------------------------------------
// Single fused kernel. Each block builds the (tiny) spline tables in shared:
//   warp0: widths (softmax->cumsum->rbw + boundaries)
//   warp1: heights (ch, bh)
//   warp2: derivatives (softplus)
//   then all 256 threads: 128-cell uniform-grid LUT (binary search)
// Tables are [idx][dim]-transposed -> all gathers bank-conflict-free.
// Main loop: one warp per 2 rows/trip; lane handles cols {lane, lane+32}.
// ---------------------------------------------------------------------------
__global__ __launch_bounds__(256, 6)
void rqs_forward_kernel(const float* __restrict__ u,
                        const float* __restrict__ w,
                        const float* __restrict__ h,
                        const float* __restrict__ dk,
                        const int*   __restrict__ nodes,
                        float* __restrict__ xout,
                        float* __restrict__ logd)
{
    __shared__ float         s_bndT[(KK + 1) * DD];   // cumw[k], k=0..39; row40=+INF  (5.25 KB)
    __shared__ float4        s_t0T [(KK + 1) * DD];   // {rbw, ch, bh, d0}; row40.w=1  (21 KB)
    __shared__ unsigned char s_lutT[NCELL * DD];      // 4 KB
    __shared__ int           s_inv [DTOT];

    const int tid  = threadIdx.x;
    const int lane = tid & 31;
    const int warp = tid >> 5;

    // ---- Phase A: build tables (3 warps in parallel, 1 dim per lane) ----
    if (tid < DTOT) s_inv[tid] = -1;

    if (warp == 0) {                       // widths -> rbw (.x), boundaries
        const int j = lane;
        const float* row = w + j * KK;
        float mx = -1e30f;
        for (int k = 0; k < KK; k++) mx = fmaxf(mx, row[k]);
        float s = 0.f;
        for (int k = 0; k < KK; k++) s += __expf(row[k] - mx);
        const float inv_s = (2.0f * BB) / s;
        float cum = -BB;
        for (int k = 0; k < KK; k++) {
            s_bndT[k * DD + j] = cum;
            const float wd = __expf(row[k] - mx) * inv_s;
            s_t0T[k * DD + j].x = 1.0f / wd;
            cum += wd;
        }
        s_bndT[KK * DD + j] = __int_as_float(0x7f800000);  // +INF probe sentinel
    } else if (warp == 1) {                // heights -> ch (.y), bh (.z)
        const int j = lane;
        const float* row = h + j * KK;
        float mx = -1e30f;
        for (int k = 0; k < KK; k++) mx = fmaxf(mx, row[k]);
        float s = 0.f;
        for (int k = 0; k < KK; k++) s += __expf(row[k] - mx);
        const float inv_s = (2.0f * BB) / s;
        float cum = -BB;
        for (int k = 0; k < KK; k++) {
            const float ht = __expf(row[k] - mx) * inv_s;
            s_t0T[k * DD + j].y = cum;
            s_t0T[k * DD + j].z = ht;
            cum += ht;
        }
    } else if (warp == 2) {                // derivatives -> d0 (.w); d1[k] = .w of row k+1
        const int j = lane;
        s_t0T[0 * DD + j].w  = 1.0f;
        s_t0T[KK * DD + j].w = 1.0f;       // derivs[40] (read as d1 when idx=39)
        const float* row = dk + j * (KK - 1);
        for (int k = 0; k < KK - 1; k++) {
            const float v = row[k];
            s_t0T[(k + 1) * DD + j].w = (v > 20.0f) ? v : log1pf(__expf(v));
        }
    }
    __syncthreads();

    // ---- Phase B: LUT (all threads; i = c*32 + j matches [c][j] layout) ----
    for (int i = tid; i < NCELL * DD; i += 256) {
        const int j = i & (DD - 1);
        const int c = i >> 5;
        const float left = -BB + (float)c * (2.0f * BB / NCELL) - 1e-4f;
        int lo = 0, hi = KK;               // largest idx with bnd[idx] <= left
        #pragma unroll
        for (int it = 0; it < 6; it++) {
            const int mid = (lo + hi) >> 1;
            if (s_bndT[mid * DD + j] <= left) lo = mid; else hi = mid;
        }
        s_lutT[i] = (unsigned char)min(lo, KK - 1);
    }
    if (tid < DD) s_inv[nodes[tid]] = tid;
    __syncthreads();

    // ---- Main loop ----
    const float* s_t0x = (const float*)s_t0T;       // scalar view (d1 plane)

    const int j0 = s_inv[lane];          // dim for col = lane (distinct per lane)
    const int j1 = s_inv[lane + 32];     // dim for col = lane + 32

    const unsigned gw     = blockIdx.x * 8 + warp;
    const unsigned stride = gridDim.x * 16;

    for (unsigned r0 = gw * 2; r0 < NROWS; r0 += stride)
    {
        const unsigned r1 = r0 + 1;
        const float* up0 = u + (size_t)r0 * DTOT;
        const float* up1 = u + (size_t)r1 * DTOT;

        float xv[4], yv[4];
        xv[0] = __ldg(up0 + lane);
        xv[1] = __ldg(up0 + lane + 32);
        xv[2] = __ldg(up1 + lane);
        xv[3] = __ldg(up1 + lane + 32);

        float acc0 = 0.0f, acc1 = 0.0f;   // in log2 units

        #pragma unroll
        for (int e = 0; e < 4; e++) {
            const int   j = (e & 1) ? j1 : j0;
            const float x = xv[e];
            float y = x;

            if (j >= 0 && fabsf(x) <= BB) {
                const int cell = min((int)fmaf(x, CELL_SCALE, BB * CELL_SCALE),
                                     NCELL - 1);
                const int idx0 = (int)s_lutT[cell * DD + j];

                const float b0 = s_bndT[idx0 * DD + j];
                const float b1 = s_bndT[(idx0 + 1) * DD + j];   // +INF at row 40
                const bool  adv = (b1 <= x);
                const int   idx = idx0 + (adv ? 1 : 0);
                const float cw  = adv ? b1 : b0;

                const float4 t0 = s_t0T[idx * DD + j];           // rbw, ch, bh, d0
                const float  d1 = s_t0x[((idx + 1) * DD + j) * 4 + 3];

                const float rbw = t0.x;
                const float bh  = t0.z;
                const float d0  = t0.w;

                const float delta = bh * rbw;
                const float theta = (x - cw) * rbw;
                const float omt   = 1.0f - theta;
                const float t1m   = theta * omt;

                const float denom = fmaf(d0 + d1 - 2.0f * delta, t1m, delta);
                const float r     = __fdividef(1.0f, denom);

                y = fmaf(bh * fmaf(delta * theta, theta, d0 * t1m), r, t0.y);

                const float A = delta * delta *
                    (fmaf(d1 * theta, theta, 2.0f * delta * t1m) + d0 * omt * omt);
                const float ld = __log2f(A * r * r);
                if (e < 2) acc0 += ld; else acc1 += ld;
            }
            yv[e] = y;
        }

        float* xp0 = xout + (size_t)r0 * DTOT;
        float* xp1 = xout + (size_t)r1 * DTOT;
        xp0[lane]      = yv[0];
        xp0[lane + 32] = yv[1];
        xp1[lane]      = yv[2];
        xp1[lane + 32] = yv[3];

        // Paired warp reduction: 6 SHFL total for both rows.
        // xor16 reduces across half-warps; then each half reduces its own acc.
        acc0 += __shfl_xor_sync(0xffffffffu, acc0, 16);
        acc1 += __shfl_xor_sync(0xffffffffu, acc1, 16);
        float z = (lane < 16) ? acc0 : acc1;
        #pragma unroll
        for (int o = 8; o > 0; o >>= 1)
            z += __shfl_xor_sync(0xffffffffu, z, o);
        // lanes 0-15 hold sum(acc0); lanes 16-31 hold sum(acc1)
        if ((lane & 15) == 0)
            logd[r0 + (lane >> 4)] = z * 0.69314718056f;
    }
}

extern "C" void kernel_launch(void* const* d_in, const int* in_sizes, int n_in,
                              void* d_out, int out_size)
{
    const float* u     = (const float*)d_in[0];
    const float* w     = (const float*)d_in[1];
    const float* h     = (const float*)d_in[2];
    const float* dk    = (const float*)d_in[3];
    const int*   nodes = (const int*)  d_in[4];

    float* xout = (float*)d_out;
    float* logd = xout + (size_t)NROWS * DTOT;

    rqs_forward_kernel<<<888, 256>>>(u, w, h, dk, nodes, xout, logd);
}

// round 9
// speedup vs baseline: 1.9444x; 1.0005x over previous
#include <cuda_runtime.h>
#include <cuda_bf16.h>
#include <math.h>

#define NROWS 1048576
#define DTOT  64
#define DD    32
#define KK    40
#define BB    5.0f
#define NCELL 128
#define CELL_SCALE (NCELL / (2.0f * BB))   // 12.8

// ---------------------------------------------------------------------------
// Single fused kernel. Each block builds the (tiny) spline tables in shared:
//   warp0: widths (softmax->cumsum->rbw + boundaries)
//   warp1: heights (ch, bh)
//   warp2: derivatives (softplus) -> d0 plane (.w of t0) + separate d1 plane
//   then all 256 threads: 128-cell uniform-grid LUT (binary search)
// Tables are [idx][dim]-transposed; d1 lives in its own tightly packed float
// plane so every gather is bank-conflict-free.
// Main loop: one warp per 2 rows/trip; lane handles cols {lane, lane+32}.
// ---------------------------------------------------------------------------
__global__ __launch_bounds__(256, 6)
void rqs_forward_kernel(const float* __restrict__ u,
                        const float* __restrict__ w,
                        const float* __restrict__ h,
                        const float* __restrict__ dk,
                        const int*   __restrict__ nodes,
                        float* __restrict__ xout,
                        float* __restrict__ logd)
{
    __shared__ float         s_bndT[(KK + 1) * DD];   // cumw[k]; row40 = +INF  (5.25 KB)
    __shared__ float4        s_t0T [KK * DD];          // {rbw, ch, bh, d0}     (20 KB)
    __shared__ float         s_d1T [KK * DD];          // d1 = derivs[k+1]      (5 KB)
    __shared__ unsigned char s_lutT[NCELL * DD];       // 4 KB
    __shared__ int           s_inv [DTOT];

    const int tid  = threadIdx.x;
    const int lane = tid & 31;
    const int warp = tid >> 5;

    // ---- Phase A: build tables (3 warps in parallel, 1 dim per lane) ----
    if (tid < DTOT) s_inv[tid] = -1;

    if (warp == 0) {                       // widths -> rbw (.x), boundaries
        const int j = lane;
        const float* row = w + j * KK;
        float mx = -1e30f;
        for (int k = 0; k < KK; k++) mx = fmaxf(mx, row[k]);
        float s = 0.f;
        for (int k = 0; k < KK; k++) s += __expf(row[k] - mx);
        const float inv_s = (2.0f * BB) / s;
        float cum = -BB;
        for (int k = 0; k < KK; k++) {
            s_bndT[k * DD + j] = cum;
            const float wd = __expf(row[k] - mx) * inv_s;
            s_t0T[k * DD + j].x = 1.0f / wd;
            cum += wd;
        }
        s_bndT[KK * DD + j] = __int_as_float(0x7f800000);  // +INF probe sentinel
    } else if (warp == 1) {                // heights -> ch (.y), bh (.z)
        const int j = lane;
        const float* row = h + j * KK;
        float mx = -1e30f;
        for (int k = 0; k < KK; k++) mx = fmaxf(mx, row[k]);
        float s = 0.f;
        for (int k = 0; k < KK; k++) s += __expf(row[k] - mx);
        const float inv_s = (2.0f * BB) / s;
        float cum = -BB;
        for (int k = 0; k < KK; k++) {
            const float ht = __expf(row[k] - mx) * inv_s;
            s_t0T[k * DD + j].y = cum;
            s_t0T[k * DD + j].z = ht;
            cum += ht;
        }
    } else if (warp == 2) {                // derivatives: d0 plane + d1 plane
        const int j = lane;
        s_t0T[0 * DD + j].w        = 1.0f;   // derivs[0]
        s_d1T[(KK - 1) * DD + j]   = 1.0f;   // derivs[40]
        const float* row = dk + j * (KK - 1);
        for (int k = 0; k < KK - 1; k++) {
            const float v  = row[k];
            const float sp = (v > 20.0f) ? v : log1pf(__expf(v));  // derivs[k+1]
            s_t0T[(k + 1) * DD + j].w = sp;   // d0 for bin k+1
            s_d1T[k * DD + j]         = sp;   // d1 for bin k
        }
    }
    __syncthreads();

    // ---- Phase B: LUT (all threads; i = c*32 + j matches [c][j] layout) ----
    for (int i = tid; i < NCELL * DD; i += 256) {
        const int j = i & (DD - 1);
        const int c = i >> 5;
        const float left = -BB + (float)c * (2.0f * BB / NCELL) - 1e-4f;
        int lo = 0, hi = KK;               // largest idx with bnd[idx] <= left
        #pragma unroll
        for (int it = 0; it < 6; it++) {
            const int mid = (lo + hi) >> 1;
            if (s_bndT[mid * DD + j] <= left) lo = mid; else hi = mid;
        }
        s_lutT[i] = (unsigned char)min(lo, KK - 1);
    }
    if (tid < DD) s_inv[nodes[tid]] = tid;
    __syncthreads();

    // ---- Main loop ----
    const int j0 = s_inv[lane];          // dim for col = lane (distinct per lane)
    const int j1 = s_inv[lane + 32];     // dim for col = lane + 32

    const unsigned gw     = blockIdx.x * 8 + warp;
    const unsigned stride = gridDim.x * 16;

    for (unsigned r0 = gw * 2; r0 < NROWS; r0 += stride)
    {
        const unsigned r1 = r0 + 1;
        const float* up0 = u + (size_t)r0 * DTOT;
        const float* up1 = u + (size_t)r1 * DTOT;

        float xv[4], yv[4];
        xv[0] = __ldg(up0 + lane);
        xv[1] = __ldg(up0 + lane + 32);
        xv[2] = __ldg(up1 + lane);
        xv[3] = __ldg(up1 + lane + 32);

        float acc0 = 0.0f, acc1 = 0.0f;   // in log2 units

        #pragma unroll
        for (int e = 0; e < 4; e++) {
            const int   j = (e & 1) ? j1 : j0;
            const float x = xv[e];
            float y = x;

            if (j >= 0 && fabsf(x) <= BB) {
                const int cell = min((int)fmaf(x, CELL_SCALE, BB * CELL_SCALE),
                                     NCELL - 1);
                const int idx0 = (int)s_lutT[cell * DD + j];

                const float b0 = s_bndT[idx0 * DD + j];
                const float b1 = s_bndT[(idx0 + 1) * DD + j];   // +INF at row 40
                const bool  adv = (b1 <= x);
                const int   idx = idx0 + (adv ? 1 : 0);
                const float cw  = adv ? b1 : b0;

                const float4 t0 = s_t0T[idx * DD + j];   // rbw, ch, bh, d0
                const float  d1 = s_d1T[idx * DD + j];

                const float rbw = t0.x;
                const float bh  = t0.z;
                const float d0  = t0.w;

                const float delta = bh * rbw;
                const float theta = (x - cw) * rbw;
                const float omt   = 1.0f - theta;
                const float t1m   = theta * omt;

                const float denom = fmaf(d0 + d1 - 2.0f * delta, t1m, delta);
                const float r     = __fdividef(1.0f, denom);

                y = fmaf(bh * fmaf(delta * theta, theta, d0 * t1m), r, t0.y);

                const float A = delta * delta *
                    (fmaf(d1 * theta, theta, 2.0f * delta * t1m) + d0 * omt * omt);
                const float ld = __log2f(A * r * r);
                if (e < 2) acc0 += ld; else acc1 += ld;
            }
            yv[e] = y;
        }

        float* xp0 = xout + (size_t)r0 * DTOT;
        float* xp1 = xout + (size_t)r1 * DTOT;
        xp0[lane]      = yv[0];
        xp0[lane + 32] = yv[1];
        xp1[lane]      = yv[2];
        xp1[lane + 32] = yv[3];

        // Paired warp reduction: 6 SHFL total for both rows.
        acc0 += __shfl_xor_sync(0xffffffffu, acc0, 16);
        acc1 += __shfl_xor_sync(0xffffffffu, acc1, 16);
        float z = (lane < 16) ? acc0 : acc1;
        #pragma unroll
        for (int o = 8; o > 0; o >>= 1)
            z += __shfl_xor_sync(0xffffffffu, z, o);
        // lanes 0-15 hold sum(acc0); lanes 16-31 hold sum(acc1)
        if ((lane & 15) == 0)
            logd[r0 + (lane >> 4)] = z * 0.69314718056f;
    }
}

extern "C" void kernel_launch(void* const* d_in, const int* in_sizes, int n_in,
                              void* d_out, int out_size)
{
    const float* u     = (const float*)d_in[0];
    const float* w     = (const float*)d_in[1];
    const float* h     = (const float*)d_in[2];
    const float* dk    = (const float*)d_in[3];
    const int*   nodes = (const int*)  d_in[4];

    float* xout = (float*)d_out;
    float* logd = xout + (size_t)NROWS * DTOT;

    rqs_forward_kernel<<<888, 256>>>(u, w, h, dk, nodes, xout, logd);
}

// round 11
// speedup vs baseline: 2.1560x; 1.1088x over previous
#include <cuda_runtime.h>
#include <cuda_bf16.h>
#include <math.h>

#define NROWS 1048576
#define DTOT  64
#define DD    32
#define KK    40
#define BB    5.0f
#define NCELL 128
#define CELL_SCALE (NCELL / (2.0f * BB))   // 12.8

// ---------------------------------------------------------------------------
// Single fused kernel. Each block builds the (tiny) spline tables in shared:
//   warp0: widths (softmax->cumsum->rbw + boundaries)
//   warp1: heights (ch, bh)
//   warp2: derivatives (softplus) -> d0 plane (.w of t0) + separate d1 plane
//   then all 256 threads: 128-cell uniform-grid LUT (binary search)
// Tables are [idx][dim]-transposed -> all gathers bank-conflict-free.
// Main loop: one warp per 4 rows/trip (8 batched LDGs -> high MLP);
// lane handles cols {lane, lane+32} of each row.
// ---------------------------------------------------------------------------
__global__ __launch_bounds__(256, 5)
void rqs_forward_kernel(const float* __restrict__ u,
                        const float* __restrict__ w,
                        const float* __restrict__ h,
                        const float* __restrict__ dk,
                        const int*   __restrict__ nodes,
                        float* __restrict__ xout,
                        float* __restrict__ logd)
{
    __shared__ float         s_bndT[(KK + 1) * DD];   // cumw[k]; row40 = +INF  (5.25 KB)
    __shared__ float4        s_t0T [KK * DD];          // {rbw, ch, bh, d0}     (20 KB)
    __shared__ float         s_d1T [KK * DD];          // d1 = derivs[k+1]      (5 KB)
    __shared__ unsigned char s_lutT[NCELL * DD];       // 4 KB
    __shared__ int           s_inv [DTOT];

    const int tid  = threadIdx.x;
    const int lane = tid & 31;
    const int warp = tid >> 5;

    // ---- Phase A: build tables (3 warps in parallel, 1 dim per lane) ----
    if (tid < DTOT) s_inv[tid] = -1;

    if (warp == 0) {                       // widths -> rbw (.x), boundaries
        const int j = lane;
        const float* row = w + j * KK;
        float mx = -1e30f;
        for (int k = 0; k < KK; k++) mx = fmaxf(mx, row[k]);
        float s = 0.f;
        for (int k = 0; k < KK; k++) s += __expf(row[k] - mx);
        const float inv_s = (2.0f * BB) / s;
        float cum = -BB;
        for (int k = 0; k < KK; k++) {
            s_bndT[k * DD + j] = cum;
            const float wd = __expf(row[k] - mx) * inv_s;
            s_t0T[k * DD + j].x = 1.0f / wd;
            cum += wd;
        }
        s_bndT[KK * DD + j] = __int_as_float(0x7f800000);  // +INF probe sentinel
    } else if (warp == 1) {                // heights -> ch (.y), bh (.z)
        const int j = lane;
        const float* row = h + j * KK;
        float mx = -1e30f;
        for (int k = 0; k < KK; k++) mx = fmaxf(mx, row[k]);
        float s = 0.f;
        for (int k = 0; k < KK; k++) s += __expf(row[k] - mx);
        const float inv_s = (2.0f * BB) / s;
        float cum = -BB;
        for (int k = 0; k < KK; k++) {
            const float ht = __expf(row[k] - mx) * inv_s;
            s_t0T[k * DD + j].y = cum;
            s_t0T[k * DD + j].z = ht;
            cum += ht;
        }
    } else if (warp == 2) {                // derivatives: d0 plane + d1 plane
        const int j = lane;
        s_t0T[0 * DD + j].w        = 1.0f;   // derivs[0]
        s_d1T[(KK - 1) * DD + j]   = 1.0f;   // derivs[40]
        const float* row = dk + j * (KK - 1);
        for (int k = 0; k < KK - 1; k++) {
            const float v  = row[k];
            const float sp = (v > 20.0f) ? v : log1pf(__expf(v));  // derivs[k+1]
            s_t0T[(k + 1) * DD + j].w = sp;   // d0 for bin k+1
            s_d1T[k * DD + j]         = sp;   // d1 for bin k
        }
    }
    __syncthreads();

    // ---- Phase B: LUT (all threads; i = c*32 + j matches [c][j] layout) ----
    for (int i = tid; i < NCELL * DD; i += 256) {
        const int j = i & (DD - 1);
        const int c = i >> 5;
        const float left = -BB + (float)c * (2.0f * BB / NCELL) - 1e-4f;
        int lo = 0, hi = KK;               // largest idx with bnd[idx] <= left
        #pragma unroll
        for (int it = 0; it < 6; it++) {
            const int mid = (lo + hi) >> 1;
            if (s_bndT[mid * DD + j] <= left) lo = mid; else hi = mid;
        }
        s_lutT[i] = (unsigned char)min(lo, KK - 1);
    }
    if (tid < DD) s_inv[nodes[tid]] = tid;
    __syncthreads();

    // ---- Main loop ----
    const int j0 = s_inv[lane];          // dim for col = lane (distinct per lane)
    const int j1 = s_inv[lane + 32];     // dim for col = lane + 32

    const unsigned gw     = blockIdx.x * 8 + warp;
    const unsigned stride = gridDim.x * 8 * 4;

    for (unsigned r0 = gw * 4; r0 < NROWS; r0 += stride)
    {
        const float* up = u + (size_t)r0 * DTOT;

        // batch all 8 loads up front (4 rows x 2 cols) for MLP
        float xA[4], xB[4];
        #pragma unroll
        for (int q = 0; q < 4; q++) {
            xA[q] = __ldcs(up + q * DTOT + lane);
            xB[q] = __ldcs(up + q * DTOT + lane + 32);
        }

        float acc[4];

        #pragma unroll
        for (int q = 0; q < 4; q++) {
            float a = 0.0f;   // log2-domain row accumulator (this lane's share)

            // ---- slot A: col = lane, dim j0 ----
            {
                const int   j = j0;
                const float x = xA[q];
                float y = x;
                if (j >= 0 && fabsf(x) <= BB) {
                    const int cell = min((int)fmaf(x, CELL_SCALE, BB * CELL_SCALE),
                                         NCELL - 1);
                    const int idx0 = (int)s_lutT[cell * DD + j];
                    const float b0 = s_bndT[idx0 * DD + j];
                    const float b1 = s_bndT[(idx0 + 1) * DD + j];
                    const bool  adv = (b1 <= x);
                    const int   idx = idx0 + (adv ? 1 : 0);
                    const float cw  = adv ? b1 : b0;

                    const float4 t0 = s_t0T[idx * DD + j];   // rbw, ch, bh, d0
                    const float  d1 = s_d1T[idx * DD + j];

                    const float rbw = t0.x, bh = t0.z, d0 = t0.w;
                    const float delta = bh * rbw;
                    const float theta = (x - cw) * rbw;
                    const float omt   = 1.0f - theta;
                    const float t1m   = theta * omt;
                    const float denom = fmaf(d0 + d1 - 2.0f * delta, t1m, delta);
                    const float r     = __fdividef(1.0f, denom);
                    y = fmaf(bh * fmaf(delta * theta, theta, d0 * t1m), r, t0.y);
                    const float A = delta * delta *
                        (fmaf(d1 * theta, theta, 2.0f * delta * t1m) + d0 * omt * omt);
                    a += __log2f(A * r * r);
                }
                xA[q] = y;
            }
            // ---- slot B: col = lane + 32, dim j1 ----
            {
                const int   j = j1;
                const float x = xB[q];
                float y = x;
                if (j >= 0 && fabsf(x) <= BB) {
                    const int cell = min((int)fmaf(x, CELL_SCALE, BB * CELL_SCALE),
                                         NCELL - 1);
                    const int idx0 = (int)s_lutT[cell * DD + j];
                    const float b0 = s_bndT[idx0 * DD + j];
                    const float b1 = s_bndT[(idx0 + 1) * DD + j];
                    const bool  adv = (b1 <= x);
                    const int   idx = idx0 + (adv ? 1 : 0);
                    const float cw  = adv ? b1 : b0;

                    const float4 t0 = s_t0T[idx * DD + j];
                    const float  d1 = s_d1T[idx * DD + j];

                    const float rbw = t0.x, bh = t0.z, d0 = t0.w;
                    const float delta = bh * rbw;
                    const float theta = (x - cw) * rbw;
                    const float omt   = 1.0f - theta;
                    const float t1m   = theta * omt;
                    const float denom = fmaf(d0 + d1 - 2.0f * delta, t1m, delta);
                    const float r     = __fdividef(1.0f, denom);
                    y = fmaf(bh * fmaf(delta * theta, theta, d0 * t1m), r, t0.y);
                    const float A = delta * delta *
                        (fmaf(d1 * theta, theta, 2.0f * delta * t1m) + d0 * omt * omt);
                    a += __log2f(A * r * r);
                }
                xB[q] = y;
            }
            acc[q] = a;
        }

        // batched stores
        float* xp = xout + (size_t)r0 * DTOT;
        #pragma unroll
        for (int q = 0; q < 4; q++) {
            __stcs(xp + q * DTOT + lane,      xA[q]);
            __stcs(xp + q * DTOT + lane + 32, xB[q]);
        }

        // two paired warp reductions (6 SHFL each for 2 rows)
        #pragma unroll
        for (int p = 0; p < 2; p++) {
            float a0 = acc[2 * p], a1 = acc[2 * p + 1];
            a0 += __shfl_xor_sync(0xffffffffu, a0, 16);
            a1 += __shfl_xor_sync(0xffffffffu, a1, 16);
            float z = (lane < 16) ? a0 : a1;
            #pragma unroll
            for (int o = 8; o > 0; o >>= 1)
                z += __shfl_xor_sync(0xffffffffu, z, o);
            if ((lane & 15) == 0)
                __stcs(logd + r0 + 2 * p + (lane >> 4), z * 0.69314718056f);
        }
    }
}

extern "C" void kernel_launch(void* const* d_in, const int* in_sizes, int n_in,
                              void* d_out, int out_size)
{
    const float* u     = (const float*)d_in[0];
    const float* w     = (const float*)d_in[1];
    const float* h     = (const float*)d_in[2];
    const float* dk    = (const float*)d_in[3];
    const int*   nodes = (const int*)  d_in[4];

    float* xout = (float*)d_out;
    float* logd = xout + (size_t)NROWS * DTOT;

    rqs_forward_kernel<<<740, 256>>>(u, w, h, dk, nodes, xout, logd);
}